// round 7
// baseline (speedup 1.0000x reference)
#include <cuda_runtime.h>

#define FDIM 128
#define S_N 50000
#define T_N 50000
#define E_N 600000
#define F2 256
#define F4 512
#define SLOPE 0.1f
#define BN_EPS 1e-5f

#define BM 64
#define BN 128
#define BK 16

typedef unsigned long long ull;

__device__ __forceinline__ ull pack2(float x) {
    ull r;
    unsigned xi = __float_as_uint(x);
    asm("mov.b64 %0, {%1, %1};" : "=l"(r) : "r"(xi));
    return r;
}
__device__ __forceinline__ void ffma2(ull& d, ull a, ull b) {
    asm("fma.rn.f32x2 %0, %1, %2, %0;" : "+l"(d) : "l"(a), "l"(b));
}
__device__ __forceinline__ void unpack2(ull v, float& lo, float& hi) {
    asm("mov.b64 {%0, %1}, %2;" : "=f"(lo), "=f"(hi) : "l"(v));
}

// Scratch (device globals — no runtime allocation allowed)
__device__ float  g_P[(size_t)S_N * F2];     // x_s @ W1a_top + b1a
__device__ float  g_aggH[(size_t)T_N * F2];  // sum of leaky(layer1 out) per target
__device__ float  g_h3[(size_t)T_N * F4];    // leaky(node layer1 out)
__device__ float  g_Wmid[(size_t)F2 * F4];   // W1b @ W2a[128:384]
__device__ float  g_bvec[F4];                // b1b @ W2a[128:384]
__device__ float  g_c2[F4];                  // u @ W2a[384:512] + b2a
__device__ int    g_cnt[T_N];
__device__ double g_sum[FDIM];
__device__ double g_sumsq[FDIM];

__global__ void zero_kernel() {
    int idx = blockIdx.x * blockDim.x + threadIdx.x;
    int stride = gridDim.x * blockDim.x;
    for (size_t i = idx; i < (size_t)T_N * F2; i += stride) g_aggH[i] = 0.f;
    for (int i = idx; i < T_N; i += stride) g_cnt[i] = 0;
    if (idx < FDIM) { g_sum[idx] = 0.0; g_sumsq[idx] = 0.0; }
}

__global__ void __launch_bounds__(512) compute_Wmid(
    const float* __restrict__ W1b, const float* __restrict__ W2a)
{
    __shared__ float sRow[F2];
    int k = blockIdx.x;
    int j = threadIdx.x;
    if (j < F2) sRow[j] = W1b[(size_t)k * F2 + j];
    __syncthreads();
    float acc = 0.f;
    #pragma unroll 4
    for (int m = 0; m < F2; m++)
        acc = fmaf(sRow[m], W2a[(size_t)(128 + m) * F4 + j], acc);
    g_Wmid[(size_t)k * F4 + j] = acc;
}

__global__ void __launch_bounds__(512) compute_vecs(
    const float* __restrict__ b1b, const float* __restrict__ u,
    const float* __restrict__ W2a, const float* __restrict__ b2a)
{
    int j = threadIdx.x;
    float bv = 0.f;
    for (int m = 0; m < F2; m++)
        bv = fmaf(b1b[m], W2a[(size_t)(128 + m) * F4 + j], bv);
    g_bvec[j] = bv;
    float cv = b2a[j];
    for (int k = 0; k < FDIM; k++)
        cv = fmaf(u[k], W2a[(size_t)(384 + k) * F4 + j], cv);
    g_c2[j] = cv;
}

// ---------------------------------------------------------------------------
// Shared GEMM mainloop macro: 64x128 block, 4x8 per thread, f32x2 FMA.
// Expects: As[BK][BM+4], Bs[BK][BN+4] filled; accp[4][4] ull accumulators.
// ---------------------------------------------------------------------------
#define MAINLOOP_STEP()                                                        \
    _Pragma("unroll")                                                          \
    for (int kk = 0; kk < BK; kk++) {                                          \
        float4 a = *reinterpret_cast<const float4*>(&As[kk][ty * 4]);          \
        ull a0 = pack2(a.x), a1 = pack2(a.y), a2v = pack2(a.z), a3 = pack2(a.w);\
        const ulonglong2* bp =                                                 \
            reinterpret_cast<const ulonglong2*>(&Bs[kk][tx * 8]);              \
        ulonglong2 bA = bp[0], bB = bp[1];                                     \
        ffma2(accp[0][0], a0, bA.x); ffma2(accp[0][1], a0, bA.y);              \
        ffma2(accp[0][2], a0, bB.x); ffma2(accp[0][3], a0, bB.y);              \
        ffma2(accp[1][0], a1, bA.x); ffma2(accp[1][1], a1, bA.y);              \
        ffma2(accp[1][2], a1, bB.x); ffma2(accp[1][3], a1, bB.y);              \
        ffma2(accp[2][0], a2v, bA.x); ffma2(accp[2][1], a2v, bA.y);            \
        ffma2(accp[2][2], a2v, bB.x); ffma2(accp[2][3], a2v, bB.y);            \
        ffma2(accp[3][0], a3, bA.x); ffma2(accp[3][1], a3, bA.y);              \
        ffma2(accp[3][2], a3, bB.x); ffma2(accp[3][3], a3, bB.y);              \
    }

// ---------------------------------------------------------------------------
// P = x_s[S,128] @ W1a[0:128][256] + b1a  -> g_P
// ---------------------------------------------------------------------------
__global__ void __launch_bounds__(256) gemm_pre(
    const float* __restrict__ x_s,
    const float* __restrict__ W1a, const float* __restrict__ b1a)
{
    __shared__ __align__(16) float As[BK][BM + 4];
    __shared__ __align__(16) float Bs[BK][BN + 4];

    int tid = threadIdx.x;
    int m0 = blockIdx.y * BM;
    int n0 = blockIdx.x * BN;

    ull accp[4][4] = {};
    int ty = tid >> 4, tx = tid & 15;
    int ai = tid >> 2, akq = (tid & 3) * 4;
    int bk = tid >> 4, bn = (tid & 15) * 8;

    for (int kt = 0; kt < FDIM; kt += BK) {
        int r = m0 + ai;
        float4 av = make_float4(0.f, 0.f, 0.f, 0.f);
        if (r < S_N)
            av = *reinterpret_cast<const float4*>(x_s + (size_t)r * FDIM + kt + akq);
        As[akq + 0][ai] = av.x; As[akq + 1][ai] = av.y;
        As[akq + 2][ai] = av.z; As[akq + 3][ai] = av.w;

        const float* brow = W1a + (size_t)(kt + bk) * F2 + n0 + bn;
        *reinterpret_cast<float4*>(&Bs[bk][bn])     = *reinterpret_cast<const float4*>(brow);
        *reinterpret_cast<float4*>(&Bs[bk][bn + 4]) = *reinterpret_cast<const float4*>(brow + 4);
        __syncthreads();

        MAINLOOP_STEP();
        __syncthreads();
    }

    #pragma unroll
    for (int i = 0; i < 4; i++) {
        int r = m0 + ty * 4 + i;
        if (r >= S_N) continue;
        #pragma unroll
        for (int j = 0; j < 4; j++) {
            int n = n0 + tx * 8 + j * 2;
            float lo, hi; unpack2(accp[i][j], lo, hi);
            g_P[(size_t)r * F2 + n]     = lo + b1a[n];
            g_P[(size_t)r * F2 + n + 1] = hi + b1a[n + 1];
        }
    }
}

// ---------------------------------------------------------------------------
// Edge GEMM: edge_attr[E,128] @ W1a[128:256][256]; epilogue:
//   v = leaky(acc + P[src][n]); atomicAdd aggH[tgt][n]. Counts in col-block 0.
// ---------------------------------------------------------------------------
__global__ void __launch_bounds__(256) gemm_edge(
    const float* __restrict__ edge_attr, const int* __restrict__ eidx,
    const float* __restrict__ W1a)
{
    __shared__ __align__(16) float As[BK][BM + 4];
    __shared__ __align__(16) float Bs[BK][BN + 4];
    __shared__ int sSrc[BM];
    __shared__ int sTgt[BM];

    int tid = threadIdx.x;
    int m0 = blockIdx.y * BM;
    int n0 = blockIdx.x * BN;

    if (tid < BM) {
        int m = m0 + tid;                 // E_N divisible by BM
        sSrc[tid] = eidx[m];
        sTgt[tid] = eidx[E_N + m];
    }
    __syncthreads();
    if (blockIdx.x == 0 && tid < BM) atomicAdd(&g_cnt[sTgt[tid]], 1);

    ull accp[4][4] = {};
    int ty = tid >> 4, tx = tid & 15;
    int ai = tid >> 2, akq = (tid & 3) * 4;
    int bk = tid >> 4, bn = (tid & 15) * 8;

    for (int kt = 0; kt < FDIM; kt += BK) {
        float4 av = *reinterpret_cast<const float4*>(
            edge_attr + (size_t)(m0 + ai) * FDIM + kt + akq);
        As[akq + 0][ai] = av.x; As[akq + 1][ai] = av.y;
        As[akq + 2][ai] = av.z; As[akq + 3][ai] = av.w;

        const float* brow = W1a + (size_t)(FDIM + kt + bk) * F2 + n0 + bn;
        *reinterpret_cast<float4*>(&Bs[bk][bn])     = *reinterpret_cast<const float4*>(brow);
        *reinterpret_cast<float4*>(&Bs[bk][bn + 4]) = *reinterpret_cast<const float4*>(brow + 4);
        __syncthreads();

        MAINLOOP_STEP();
        __syncthreads();
    }

    #pragma unroll
    for (int i = 0; i < 4; i++) {
        int row = ty * 4 + i;
        int s = sSrc[row];
        int t = sTgt[row];
        const float* pp = &g_P[(size_t)s * F2 + n0 + tx * 8];
        float4 p0 = *reinterpret_cast<const float4*>(pp);
        float4 p1 = *reinterpret_cast<const float4*>(pp + 4);
        float pr[8] = {p0.x, p0.y, p0.z, p0.w, p1.x, p1.y, p1.z, p1.w};
        float* op = &g_aggH[(size_t)t * F2 + n0 + tx * 8];
        #pragma unroll
        for (int j = 0; j < 4; j++) {
            float lo, hi; unpack2(accp[i][j], lo, hi);
            float v0 = lo + pr[j * 2];
            float v1 = hi + pr[j * 2 + 1];
            v0 = v0 >= 0.f ? v0 : SLOPE * v0;
            v1 = v1 >= 0.f ? v1 : SLOPE * v1;
            atomicAdd(op + j * 2, v0);
            atomicAdd(op + j * 2 + 1, v1);
        }
    }
}

// ---------------------------------------------------------------------------
// Node GEMM 1: [T,384](= x_t | aggH) @ [W2a_top ; Wmid] (384x512)
// epilogue: v = leaky(acc + c2[n] + cnt[r]*bvec[n]) -> g_h3
// ---------------------------------------------------------------------------
__global__ void __launch_bounds__(256) gemm_node1(
    const float* __restrict__ x_t, const float* __restrict__ W2a)
{
    __shared__ __align__(16) float As[BK][BM + 4];
    __shared__ __align__(16) float Bs[BK][BN + 4];

    int tid = threadIdx.x;
    int m0 = blockIdx.y * BM;
    int n0 = blockIdx.x * BN;

    ull accp[4][4] = {};
    int ty = tid >> 4, tx = tid & 15;
    int ai = tid >> 2, akq = (tid & 3) * 4;
    int bk = tid >> 4, bn = (tid & 15) * 8;

    const int KTOT = FDIM + F2;  // 384
    for (int kt = 0; kt < KTOT; kt += BK) {
        int r = m0 + ai;
        int gk = kt + akq;
        float4 av = make_float4(0.f, 0.f, 0.f, 0.f);
        if (r < T_N) {
            if (gk < FDIM)
                av = *reinterpret_cast<const float4*>(x_t + (size_t)r * FDIM + gk);
            else
                av = *reinterpret_cast<const float4*>(&g_aggH[(size_t)r * F2 + gk - FDIM]);
        }
        As[akq + 0][ai] = av.x; As[akq + 1][ai] = av.y;
        As[akq + 2][ai] = av.z; As[akq + 3][ai] = av.w;

        int gkb = kt + bk;
        const float* brow;
        if (gkb < FDIM) brow = W2a + (size_t)gkb * F4 + n0 + bn;
        else            brow = &g_Wmid[(size_t)(gkb - FDIM) * F4 + n0 + bn];
        *reinterpret_cast<float4*>(&Bs[bk][bn])     = *reinterpret_cast<const float4*>(brow);
        *reinterpret_cast<float4*>(&Bs[bk][bn + 4]) = *reinterpret_cast<const float4*>(brow + 4);
        __syncthreads();

        MAINLOOP_STEP();
        __syncthreads();
    }

    #pragma unroll
    for (int i = 0; i < 4; i++) {
        int r = m0 + ty * 4 + i;
        if (r >= T_N) continue;
        float c = (float)g_cnt[r];
        #pragma unroll
        for (int j = 0; j < 4; j++) {
            int n = n0 + tx * 8 + j * 2;
            float lo, hi; unpack2(accp[i][j], lo, hi);
            float v0 = lo + g_c2[n]     + c * g_bvec[n];
            float v1 = hi + g_c2[n + 1] + c * g_bvec[n + 1];
            v0 = v0 >= 0.f ? v0 : SLOPE * v0;
            v1 = v1 >= 0.f ? v1 : SLOPE * v1;
            g_h3[(size_t)r * F4 + n]     = v0;
            g_h3[(size_t)r * F4 + n + 1] = v1;
        }
    }
}

// ---------------------------------------------------------------------------
// Node GEMM 2: g_h3[T,512] @ W2b[512,128], epilogue +b2b -> out (pre-BN y)
// ---------------------------------------------------------------------------
__global__ void __launch_bounds__(256) gemm_node2(
    const float* __restrict__ W2b, const float* __restrict__ b2b,
    float* __restrict__ out)
{
    __shared__ __align__(16) float As[BK][BM + 4];
    __shared__ __align__(16) float Bs[BK][BN + 4];

    int tid = threadIdx.x;
    int m0 = blockIdx.y * BM;
    int n0 = 0;  // N = 128 = BN, single column block

    ull accp[4][4] = {};
    int ty = tid >> 4, tx = tid & 15;
    int ai = tid >> 2, akq = (tid & 3) * 4;
    int bk = tid >> 4, bn = (tid & 15) * 8;

    for (int kt = 0; kt < F4; kt += BK) {
        int r = m0 + ai;
        float4 av = make_float4(0.f, 0.f, 0.f, 0.f);
        if (r < T_N)
            av = *reinterpret_cast<const float4*>(&g_h3[(size_t)r * F4 + kt + akq]);
        As[akq + 0][ai] = av.x; As[akq + 1][ai] = av.y;
        As[akq + 2][ai] = av.z; As[akq + 3][ai] = av.w;

        const float* brow = W2b + (size_t)(kt + bk) * FDIM + n0 + bn;
        *reinterpret_cast<float4*>(&Bs[bk][bn])     = *reinterpret_cast<const float4*>(brow);
        *reinterpret_cast<float4*>(&Bs[bk][bn + 4]) = *reinterpret_cast<const float4*>(brow + 4);
        __syncthreads();

        MAINLOOP_STEP();
        __syncthreads();
    }

    #pragma unroll
    for (int i = 0; i < 4; i++) {
        int r = m0 + ty * 4 + i;
        if (r >= T_N) continue;
        #pragma unroll
        for (int j = 0; j < 4; j++) {
            int n = n0 + tx * 8 + j * 2;
            float lo, hi; unpack2(accp[i][j], lo, hi);
            out[(size_t)r * FDIM + n]     = lo + b2b[n];
            out[(size_t)r * FDIM + n + 1] = hi + b2b[n + 1];
        }
    }
}

// ---------------------------------------------------------------------------
// BatchNorm: column stats (double accum) then normalize in place
// ---------------------------------------------------------------------------
__global__ void bn_stats(const float* __restrict__ y) {
    int c = threadIdx.x & (FDIM - 1);
    int half = threadIdx.x >> 7;
    double s = 0.0, sq = 0.0;
    for (int m = blockIdx.x * 2 + half; m < T_N; m += gridDim.x * 2) {
        float v = y[(size_t)m * FDIM + c];
        s += v;
        sq += (double)v * (double)v;
    }
    atomicAdd(&g_sum[c], s);
    atomicAdd(&g_sumsq[c], sq);
}

__global__ void bn_norm(float* __restrict__ y,
                        const float* __restrict__ gamma,
                        const float* __restrict__ beta) {
    size_t idx = (size_t)blockIdx.x * blockDim.x + threadIdx.x;
    if (idx >= (size_t)T_N * FDIM) return;
    int c = (int)(idx & (FDIM - 1));
    double mean = g_sum[c] / (double)T_N;
    double var = g_sumsq[c] / (double)T_N - mean * mean;
    float scale = rsqrtf((float)var + BN_EPS) * gamma[c];
    y[idx] = (float)((double)y[idx] - mean) * scale + beta[c];
}

extern "C" void kernel_launch(void* const* d_in, const int* in_sizes, int n_in,
                              void* d_out, int out_size) {
    const float* x_s       = (const float*)d_in[0];
    const float* x_t       = (const float*)d_in[1];
    const float* edge_attr = (const float*)d_in[2];
    const float* u         = (const float*)d_in[3];
    const int*   eidx      = (const int*)d_in[4];
    const float* W1a       = (const float*)d_in[5];
    const float* b1a       = (const float*)d_in[6];
    const float* W1b       = (const float*)d_in[7];
    const float* b1b       = (const float*)d_in[8];
    const float* W2a       = (const float*)d_in[9];
    const float* b2a       = (const float*)d_in[10];
    const float* W2b       = (const float*)d_in[11];
    const float* b2b       = (const float*)d_in[12];
    const float* gamma     = (const float*)d_in[13];
    const float* beta      = (const float*)d_in[14];
    float* out = (float*)d_out;

    zero_kernel<<<1024, 256>>>();
    compute_Wmid<<<F2, 512>>>(W1b, W2a);
    compute_vecs<<<1, 512>>>(b1b, u, W2a, b2a);

    int sblk = (S_N + BM - 1) / BM;             // 782
    dim3 gP(F2 / BN, sblk);                     // (2, 782)
    gemm_pre<<<gP, 256>>>(x_s, W1a, b1a);

    dim3 gE(F2 / BN, E_N / BM);                 // (2, 9375)
    gemm_edge<<<gE, 256>>>(edge_attr, eidx, W1a);

    int mblk = (T_N + BM - 1) / BM;             // 782
    dim3 gN1(F4 / BN, mblk);                    // (4, 782)
    gemm_node1<<<gN1, 256>>>(x_t, W2a);

    dim3 gN2(1, mblk);
    gemm_node2<<<gN2, 256>>>(W2b, b2b, out);

    bn_stats<<<512, 256>>>(out);
    bn_norm<<<(T_N * FDIM + 255) / 256, 256>>>(out, gamma, beta);
}

// round 9
// speedup vs baseline: 2.5477x; 2.5477x over previous
#include <cuda_runtime.h>
#include <cuda_bf16.h>
#include <cstdint>

#define FDIM 128
#define S_N 50000
#define T_N 50000
#define E_N 600000
#define F2 256
#define F4 512
#define SLOPE 0.1f
#define BN_EPS 1e-5f

#define PA 40          // smem pitch in bf16 elems (80B rows: conflict-free ldmatrix)
#define TBM 128        // CTA tile M
#define TBN 64         // CTA tile N
#define TBK 32         // K chunk (two k16 steps)

// ---------------------------------------------------------------------------
// Scratch (device globals — no runtime allocation allowed)
// ---------------------------------------------------------------------------
__device__ float  g_P[(size_t)S_N * F2];
__device__ float  g_aggH[(size_t)T_N * F2];
__device__ float  g_h3[(size_t)T_N * F4];
__device__ float  g_Wmid[(size_t)F2 * F4];
__device__ float  g_bvec[F4];
__device__ float  g_c2[F4];
__device__ int    g_cnt[T_N];
__device__ double g_sum[FDIM];
__device__ double g_sumsq[FDIM];
// Pre-split bf16 weights, transposed to [n][k]
__device__ __align__(16) __nv_bfloat16 g_Bpre_hi[(size_t)F2 * FDIM];
__device__ __align__(16) __nv_bfloat16 g_Bpre_lo[(size_t)F2 * FDIM];
__device__ __align__(16) __nv_bfloat16 g_Bedge_hi[(size_t)F2 * FDIM];
__device__ __align__(16) __nv_bfloat16 g_Bedge_lo[(size_t)F2 * FDIM];
__device__ __align__(16) __nv_bfloat16 g_Bn1_hi[(size_t)F4 * 384];
__device__ __align__(16) __nv_bfloat16 g_Bn1_lo[(size_t)F4 * 384];
__device__ __align__(16) __nv_bfloat16 g_Bn2_hi[(size_t)FDIM * F4];
__device__ __align__(16) __nv_bfloat16 g_Bn2_lo[(size_t)FDIM * F4];

// ---------------------------------------------------------------------------
// Helpers
// ---------------------------------------------------------------------------
__device__ __forceinline__ unsigned smem_u32(const void* p) {
    unsigned a;
    asm("{ .reg .u64 t; cvta.to.shared.u64 t, %1; cvt.u32.u64 %0, t; }"
        : "=r"(a) : "l"(p));
    return a;
}
__device__ __forceinline__ void ldsm4(unsigned& r0, unsigned& r1, unsigned& r2,
                                      unsigned& r3, unsigned addr) {
    asm volatile("ldmatrix.sync.aligned.m8n8.x4.shared.b16 {%0,%1,%2,%3}, [%4];"
                 : "=r"(r0), "=r"(r1), "=r"(r2), "=r"(r3) : "r"(addr));
}
__device__ __forceinline__ void mma16816(float* c, const unsigned* a, const unsigned* b) {
    asm volatile(
        "mma.sync.aligned.m16n8k16.row.col.f32.bf16.bf16.f32 "
        "{%0,%1,%2,%3}, {%4,%5,%6,%7}, {%8,%9}, {%0,%1,%2,%3};"
        : "+f"(c[0]), "+f"(c[1]), "+f"(c[2]), "+f"(c[3])
        : "r"(a[0]), "r"(a[1]), "r"(a[2]), "r"(a[3]), "r"(b[0]), "r"(b[1]));
}
__device__ __forceinline__ void split_store(__nv_bfloat16* ph, __nv_bfloat16* pl, float2 v) {
    __nv_bfloat16 hx = __float2bfloat16_rn(v.x);
    __nv_bfloat16 hy = __float2bfloat16_rn(v.y);
    __nv_bfloat16 lx = __float2bfloat16_rn(v.x - __bfloat162float(hx));
    __nv_bfloat16 ly = __float2bfloat16_rn(v.y - __bfloat162float(hy));
    __nv_bfloat162 h; h.x = hx; h.y = hy;
    __nv_bfloat162 l; l.x = lx; l.y = ly;
    *reinterpret_cast<__nv_bfloat162*>(ph) = h;
    *reinterpret_cast<__nv_bfloat162*>(pl) = l;
}

// One K=32 chunk of warp-level split-bf16 MMAs.
// aH/aL/bH/bL: per-lane ldmatrix byte addresses (ks=0, mi/nb=0 tile).
__device__ __forceinline__ void mma_chunk(unsigned aH, unsigned aL,
                                          unsigned bH, unsigned bL,
                                          float acc[2][4][4]) {
    const unsigned mstep = 16 * PA * 2;   // next m16 tile
    const unsigned nstep = 16 * PA * 2;   // next pair of n8 tiles
    #pragma unroll
    for (int ks = 0; ks < 2; ks++) {
        unsigned ko = ks * 32;            // 16 bf16 = 32 bytes
        unsigned ah[2][4], al[2][4], bh[8], bl[8];
        ldsm4(ah[0][0], ah[0][1], ah[0][2], ah[0][3], aH + ko);
        ldsm4(ah[1][0], ah[1][1], ah[1][2], ah[1][3], aH + mstep + ko);
        ldsm4(al[0][0], al[0][1], al[0][2], al[0][3], aL + ko);
        ldsm4(al[1][0], al[1][1], al[1][2], al[1][3], aL + mstep + ko);
        ldsm4(bh[0], bh[1], bh[2], bh[3], bH + ko);
        ldsm4(bh[4], bh[5], bh[6], bh[7], bH + nstep + ko);
        ldsm4(bl[0], bl[1], bl[2], bl[3], bL + ko);
        ldsm4(bl[4], bl[5], bl[6], bl[7], bL + nstep + ko);
        #pragma unroll
        for (int mi = 0; mi < 2; mi++)
            #pragma unroll
            for (int ni = 0; ni < 4; ni++) {
                mma16816(acc[mi][ni], ah[mi], &bh[2 * ni]);
                mma16816(acc[mi][ni], ah[mi], &bl[2 * ni]);
                mma16816(acc[mi][ni], al[mi], &bh[2 * ni]);
            }
    }
}

// Per-lane smem base addresses for ldmatrix
#define MAKE_ADDRS()                                                            \
    int lane = threadIdx.x & 31;                                                \
    int warp = threadIdx.x >> 5;                                                \
    int wm0 = (warp >> 1) * 32;                                                 \
    int wn0 = (warp & 1) * 32;                                                  \
    unsigned aH = smem_u32(sAh) +                                               \
        ((wm0 + ((lane >> 3) & 1) * 8 + (lane & 7)) * PA + (lane >> 4) * 8) * 2;\
    unsigned aL = smem_u32(sAl) +                                               \
        ((wm0 + ((lane >> 3) & 1) * 8 + (lane & 7)) * PA + (lane >> 4) * 8) * 2;\
    unsigned bHa = smem_u32(sBh) +                                              \
        ((wn0 + (lane >> 4) * 8 + (lane & 7)) * PA + ((lane >> 3) & 1) * 8) * 2;\
    unsigned bLa = smem_u32(sBl) +                                              \
        ((wn0 + (lane >> 4) * 8 + (lane & 7)) * PA + ((lane >> 3) & 1) * 8) * 2;

// B chunk loader from pre-split global [n][K]
#define LOAD_B(Bhi, Blo, K)                                                     \
    {                                                                           \
        int p = threadIdx.x;  /* 256 threads == 256 chunks of 8 bf16 */         \
        int n = p >> 2, j = p & 3;                                              \
        *reinterpret_cast<uint4*>(&sBh[n * PA + 8 * j]) =                       \
            *reinterpret_cast<const uint4*>(&Bhi[(size_t)(n0 + n) * (K) + kt + 8 * j]); \
        *reinterpret_cast<uint4*>(&sBl[n * PA + 8 * j]) =                       \
            *reinterpret_cast<const uint4*>(&Blo[(size_t)(n0 + n) * (K) + kt + 8 * j]); \
    }

// ---------------------------------------------------------------------------
__global__ void zero_kernel() {
    int idx = blockIdx.x * blockDim.x + threadIdx.x;
    int stride = gridDim.x * blockDim.x;
    for (size_t i = idx; i < (size_t)T_N * F2; i += stride) g_aggH[i] = 0.f;
    for (int i = idx; i < T_N; i += stride) g_cnt[i] = 0;
    if (idx < FDIM) { g_sum[idx] = 0.0; g_sumsq[idx] = 0.0; }
}

__global__ void __launch_bounds__(512) compute_Wmid(
    const float* __restrict__ W1b, const float* __restrict__ W2a)
{
    __shared__ float sRow[F2];
    int k = blockIdx.x;
    int j = threadIdx.x;
    if (j < F2) sRow[j] = W1b[(size_t)k * F2 + j];
    __syncthreads();
    float acc = 0.f;
    #pragma unroll 4
    for (int m = 0; m < F2; m++)
        acc = fmaf(sRow[m], W2a[(size_t)(128 + m) * F4 + j], acc);
    g_Wmid[(size_t)k * F4 + j] = acc;
}

__global__ void __launch_bounds__(512) compute_vecs(
    const float* __restrict__ b1b, const float* __restrict__ u,
    const float* __restrict__ W2a, const float* __restrict__ b2a)
{
    int j = threadIdx.x;
    float bv = 0.f;
    for (int m = 0; m < F2; m++)
        bv = fmaf(b1b[m], W2a[(size_t)(128 + m) * F4 + j], bv);
    g_bvec[j] = bv;
    float cv = b2a[j];
    for (int k = 0; k < FDIM; k++)
        cv = fmaf(u[k], W2a[(size_t)(384 + k) * F4 + j], cv);
    g_c2[j] = cv;
}

// Weight prep: split + transpose to [n][k]
__device__ __forceinline__ void split1(__nv_bfloat16* ph, __nv_bfloat16* pl, float v) {
    __nv_bfloat16 h = __float2bfloat16_rn(v);
    *ph = h;
    *pl = __float2bfloat16_rn(v - __bfloat162float(h));
}
__global__ void convert_Bpre(const float* __restrict__ W1a) {
    int idx = blockIdx.x * blockDim.x + threadIdx.x;
    if (idx >= F2 * FDIM) return;
    int n = idx >> 7, k = idx & 127;
    split1(&g_Bpre_hi[idx], &g_Bpre_lo[idx], W1a[(size_t)k * F2 + n]);
}
__global__ void convert_Bedge(const float* __restrict__ W1a) {
    int idx = blockIdx.x * blockDim.x + threadIdx.x;
    if (idx >= F2 * FDIM) return;
    int n = idx >> 7, k = idx & 127;
    split1(&g_Bedge_hi[idx], &g_Bedge_lo[idx], W1a[(size_t)(FDIM + k) * F2 + n]);
}
__global__ void convert_Bn1(const float* __restrict__ W2a) {
    int idx = blockIdx.x * blockDim.x + threadIdx.x;
    if (idx >= F4 * 384) return;
    int n = idx / 384, k = idx % 384;
    float v = (k < FDIM) ? W2a[(size_t)k * F4 + n] : g_Wmid[(size_t)(k - FDIM) * F4 + n];
    split1(&g_Bn1_hi[idx], &g_Bn1_lo[idx], v);
}
__global__ void convert_Bn2(const float* __restrict__ W2b) {
    int idx = blockIdx.x * blockDim.x + threadIdx.x;
    if (idx >= FDIM * F4) return;
    int n = idx >> 9, k = idx & 511;
    split1(&g_Bn2_hi[idx], &g_Bn2_lo[idx], W2b[(size_t)k * FDIM + n]);
}

// ---------------------------------------------------------------------------
// GEMM pre: x_s[S,128] @ Bpre^T -> g_P (+ b1a)
// ---------------------------------------------------------------------------
__global__ void __launch_bounds__(256) gemm_pre(
    const float* __restrict__ x_s, const float* __restrict__ b1a)
{
    __shared__ __align__(16) __nv_bfloat16 sAh[TBM * PA], sAl[TBM * PA];
    __shared__ __align__(16) __nv_bfloat16 sBh[TBN * PA], sBl[TBN * PA];
    int m0 = blockIdx.y * TBM;
    int n0 = blockIdx.x * TBN;
    float acc[2][4][4] = {};
    MAKE_ADDRS();

    for (int kt = 0; kt < FDIM; kt += TBK) {
        for (int p = threadIdx.x; p < TBM * 16; p += 256) {
            int row = p >> 4, cp = p & 15;
            int gm = m0 + row;
            float2 v = make_float2(0.f, 0.f);
            if (gm < S_N)
                v = *reinterpret_cast<const float2*>(x_s + (size_t)gm * FDIM + kt + 2 * cp);
            split_store(&sAh[row * PA + 2 * cp], &sAl[row * PA + 2 * cp], v);
        }
        LOAD_B(g_Bpre_hi, g_Bpre_lo, FDIM);
        __syncthreads();
        mma_chunk(aH, aL, bHa, bLa, acc);
        __syncthreads();
    }

    #pragma unroll
    for (int mi = 0; mi < 2; mi++)
        #pragma unroll
        for (int h = 0; h < 2; h++) {
            int r = wm0 + mi * 16 + (lane >> 2) + h * 8;
            int gm = m0 + r;
            if (gm >= S_N) continue;
            #pragma unroll
            for (int ni = 0; ni < 4; ni++) {
                int col = n0 + wn0 + ni * 8 + 2 * (lane & 3);
                float2 bb = *reinterpret_cast<const float2*>(b1a + col);
                float2 o;
                o.x = acc[mi][ni][h * 2 + 0] + bb.x;
                o.y = acc[mi][ni][h * 2 + 1] + bb.y;
                *reinterpret_cast<float2*>(&g_P[(size_t)gm * F2 + col]) = o;
            }
        }
}

// ---------------------------------------------------------------------------
// GEMM edge: edge_attr[E,128] @ Bedge^T; epi: leaky(D + P[src]) atomic-> aggH
// ---------------------------------------------------------------------------
__global__ void __launch_bounds__(256) gemm_edge(
    const float* __restrict__ edge_attr, const int* __restrict__ eidx)
{
    __shared__ __align__(16) __nv_bfloat16 sAh[TBM * PA], sAl[TBM * PA];
    __shared__ __align__(16) __nv_bfloat16 sBh[TBN * PA], sBl[TBN * PA];
    __shared__ int sSrc[TBM], sTgt[TBM];
    int m0 = blockIdx.y * TBM;
    int n0 = blockIdx.x * TBN;

    if (threadIdx.x < TBM) {
        int m = m0 + threadIdx.x;
        int sv = 0, tv = 0;
        if (m < E_N) {
            sv = eidx[m];
            tv = eidx[E_N + m];
            if (blockIdx.x == 0) atomicAdd(&g_cnt[tv], 1);
        }
        sSrc[threadIdx.x] = sv;
        sTgt[threadIdx.x] = tv;
    }

    float acc[2][4][4] = {};
    MAKE_ADDRS();

    for (int kt = 0; kt < FDIM; kt += TBK) {
        for (int p = threadIdx.x; p < TBM * 16; p += 256) {
            int row = p >> 4, cp = p & 15;
            int gm = m0 + row;
            float2 v = make_float2(0.f, 0.f);
            if (gm < E_N)
                v = *reinterpret_cast<const float2*>(edge_attr + (size_t)gm * FDIM + kt + 2 * cp);
            split_store(&sAh[row * PA + 2 * cp], &sAl[row * PA + 2 * cp], v);
        }
        LOAD_B(g_Bedge_hi, g_Bedge_lo, FDIM);
        __syncthreads();
        mma_chunk(aH, aL, bHa, bLa, acc);
        __syncthreads();
    }

    #pragma unroll
    for (int mi = 0; mi < 2; mi++)
        #pragma unroll
        for (int h = 0; h < 2; h++) {
            int r = wm0 + mi * 16 + (lane >> 2) + h * 8;
            int gm = m0 + r;
            if (gm >= E_N) continue;
            int s = sSrc[r], t = sTgt[r];
            #pragma unroll
            for (int ni = 0; ni < 4; ni++) {
                int col = n0 + wn0 + ni * 8 + 2 * (lane & 3);
                float2 pv = *reinterpret_cast<const float2*>(&g_P[(size_t)s * F2 + col]);
                float v0 = acc[mi][ni][h * 2 + 0] + pv.x;
                float v1 = acc[mi][ni][h * 2 + 1] + pv.y;
                v0 = v0 >= 0.f ? v0 : SLOPE * v0;
                v1 = v1 >= 0.f ? v1 : SLOPE * v1;
                atomicAdd(&g_aggH[(size_t)t * F2 + col], v0);
                atomicAdd(&g_aggH[(size_t)t * F2 + col + 1], v1);
            }
        }
}

// ---------------------------------------------------------------------------
// GEMM node1: [x_t | aggH][T,384] @ Bn1^T; epi leaky(+c2+cnt*bvec) -> g_h3
// ---------------------------------------------------------------------------
__global__ void __launch_bounds__(256) gemm_node1(const float* __restrict__ x_t)
{
    __shared__ __align__(16) __nv_bfloat16 sAh[TBM * PA], sAl[TBM * PA];
    __shared__ __align__(16) __nv_bfloat16 sBh[TBN * PA], sBl[TBN * PA];
    int m0 = blockIdx.y * TBM;
    int n0 = blockIdx.x * TBN;
    float acc[2][4][4] = {};
    MAKE_ADDRS();

    for (int kt = 0; kt < 384; kt += TBK) {
        for (int p = threadIdx.x; p < TBM * 16; p += 256) {
            int row = p >> 4, cp = p & 15;
            int gm = m0 + row;
            int gk = kt + 2 * cp;
            float2 v = make_float2(0.f, 0.f);
            if (gm < T_N) {
                if (gk < FDIM)
                    v = *reinterpret_cast<const float2*>(x_t + (size_t)gm * FDIM + gk);
                else
                    v = *reinterpret_cast<const float2*>(&g_aggH[(size_t)gm * F2 + gk - FDIM]);
            }
            split_store(&sAh[row * PA + 2 * cp], &sAl[row * PA + 2 * cp], v);
        }
        LOAD_B(g_Bn1_hi, g_Bn1_lo, 384);
        __syncthreads();
        mma_chunk(aH, aL, bHa, bLa, acc);
        __syncthreads();
    }

    #pragma unroll
    for (int mi = 0; mi < 2; mi++)
        #pragma unroll
        for (int h = 0; h < 2; h++) {
            int r = wm0 + mi * 16 + (lane >> 2) + h * 8;
            int gm = m0 + r;
            if (gm >= T_N) continue;
            float c = (float)g_cnt[gm];
            #pragma unroll
            for (int ni = 0; ni < 4; ni++) {
                int col = n0 + wn0 + ni * 8 + 2 * (lane & 3);
                float2 c2v = *reinterpret_cast<const float2*>(&g_c2[col]);
                float2 bvv = *reinterpret_cast<const float2*>(&g_bvec[col]);
                float v0 = acc[mi][ni][h * 2 + 0] + c2v.x + c * bvv.x;
                float v1 = acc[mi][ni][h * 2 + 1] + c2v.y + c * bvv.y;
                v0 = v0 >= 0.f ? v0 : SLOPE * v0;
                v1 = v1 >= 0.f ? v1 : SLOPE * v1;
                float2 o; o.x = v0; o.y = v1;
                *reinterpret_cast<float2*>(&g_h3[(size_t)gm * F4 + col]) = o;
            }
        }
}

// ---------------------------------------------------------------------------
// GEMM node2: g_h3[T,512] @ Bn2^T (+b2b) -> out
// ---------------------------------------------------------------------------
__global__ void __launch_bounds__(256) gemm_node2(
    const float* __restrict__ b2b, float* __restrict__ out)
{
    __shared__ __align__(16) __nv_bfloat16 sAh[TBM * PA], sAl[TBM * PA];
    __shared__ __align__(16) __nv_bfloat16 sBh[TBN * PA], sBl[TBN * PA];
    int m0 = blockIdx.y * TBM;
    int n0 = blockIdx.x * TBN;
    float acc[2][4][4] = {};
    MAKE_ADDRS();

    for (int kt = 0; kt < F4; kt += TBK) {
        for (int p = threadIdx.x; p < TBM * 16; p += 256) {
            int row = p >> 4, cp = p & 15;
            int gm = m0 + row;
            float2 v = make_float2(0.f, 0.f);
            if (gm < T_N)
                v = *reinterpret_cast<const float2*>(&g_h3[(size_t)gm * F4 + kt + 2 * cp]);
            split_store(&sAh[row * PA + 2 * cp], &sAl[row * PA + 2 * cp], v);
        }
        LOAD_B(g_Bn2_hi, g_Bn2_lo, F4);
        __syncthreads();
        mma_chunk(aH, aL, bHa, bLa, acc);
        __syncthreads();
    }

    #pragma unroll
    for (int mi = 0; mi < 2; mi++)
        #pragma unroll
        for (int h = 0; h < 2; h++) {
            int r = wm0 + mi * 16 + (lane >> 2) + h * 8;
            int gm = m0 + r;
            if (gm >= T_N) continue;
            #pragma unroll
            for (int ni = 0; ni < 4; ni++) {
                int col = n0 + wn0 + ni * 8 + 2 * (lane & 3);
                float2 bb = *reinterpret_cast<const float2*>(b2b + col);
                float2 o;
                o.x = acc[mi][ni][h * 2 + 0] + bb.x;
                o.y = acc[mi][ni][h * 2 + 1] + bb.y;
                *reinterpret_cast<float2*>(&out[(size_t)gm * FDIM + col]) = o;
            }
        }
}

// ---------------------------------------------------------------------------
// BatchNorm
// ---------------------------------------------------------------------------
__global__ void bn_stats(const float* __restrict__ y) {
    int c = threadIdx.x & (FDIM - 1);
    int half = threadIdx.x >> 7;
    double s = 0.0, sq = 0.0;
    for (int m = blockIdx.x * 2 + half; m < T_N; m += gridDim.x * 2) {
        float v = y[(size_t)m * FDIM + c];
        s += v;
        sq += (double)v * (double)v;
    }
    atomicAdd(&g_sum[c], s);
    atomicAdd(&g_sumsq[c], sq);
}

__global__ void bn_norm(float* __restrict__ y,
                        const float* __restrict__ gamma,
                        const float* __restrict__ beta) {
    size_t idx = (size_t)blockIdx.x * blockDim.x + threadIdx.x;
    if (idx >= (size_t)T_N * FDIM) return;
    int c = (int)(idx & (FDIM - 1));
    double mean = g_sum[c] / (double)T_N;
    double var = g_sumsq[c] / (double)T_N - mean * mean;
    float scale = rsqrtf((float)var + BN_EPS) * gamma[c];
    y[idx] = (float)((double)y[idx] - mean) * scale + beta[c];
}

extern "C" void kernel_launch(void* const* d_in, const int* in_sizes, int n_in,
                              void* d_out, int out_size) {
    const float* x_s       = (const float*)d_in[0];
    const float* x_t       = (const float*)d_in[1];
    const float* edge_attr = (const float*)d_in[2];
    const float* u         = (const float*)d_in[3];
    const int*   eidx      = (const int*)d_in[4];
    const float* W1a       = (const float*)d_in[5];
    const float* b1a       = (const float*)d_in[6];
    const float* W1b       = (const float*)d_in[7];
    const float* b1b       = (const float*)d_in[8];
    const float* W2a       = (const float*)d_in[9];
    const float* b2a       = (const float*)d_in[10];
    const float* W2b       = (const float*)d_in[11];
    const float* b2b       = (const float*)d_in[12];
    const float* gamma     = (const float*)d_in[13];
    const float* beta      = (const float*)d_in[14];
    float* out = (float*)d_out;

    zero_kernel<<<1024, 256>>>();
    compute_Wmid<<<F2, 512>>>(W1b, W2a);
    compute_vecs<<<1, 512>>>(b1b, u, W2a, b2a);
    convert_Bpre<<<(F2 * FDIM + 255) / 256, 256>>>(W1a);
    convert_Bedge<<<(F2 * FDIM + 255) / 256, 256>>>(W1a);
    convert_Bn1<<<(F4 * 384 + 255) / 256, 256>>>(W2a);
    convert_Bn2<<<(FDIM * F4 + 255) / 256, 256>>>(W2b);

    dim3 gP(F2 / TBN, (S_N + TBM - 1) / TBM);       // (4, 391)
    gemm_pre<<<gP, 256>>>(x_s, b1a);

    dim3 gE(F2 / TBN, (E_N + TBM - 1) / TBM);       // (4, 4688)
    gemm_edge<<<gE, 256>>>(edge_attr, eidx);

    dim3 gN1(F4 / TBN, (T_N + TBM - 1) / TBM);      // (8, 391)
    gemm_node1<<<gN1, 256>>>(x_t);

    dim3 gN2(FDIM / TBN, (T_N + TBM - 1) / TBM);    // (2, 391)
    gemm_node2<<<gN2, 256>>>(b2b, out);

    bn_stats<<<512, 256>>>(out);
    bn_norm<<<(T_N * FDIM + 255) / 256, 256>>>(out, gamma, beta);
}

// round 10
// speedup vs baseline: 2.9039x; 1.1398x over previous
#include <cuda_runtime.h>
#include <cuda_bf16.h>
#include <cstdint>

#define FDIM 128
#define S_N 50000
#define T_N 50000
#define E_N 600000
#define F2 256
#define F4 512
#define SLOPE 0.1f
#define BN_EPS 1e-5f

#define PA 24          // smem pitch (48B rows: 16B-aligned, conflict-free ldmatrix)
#define TBM 64         // CTA tile M
#define TBK 16         // K chunk (one k16 step)

// ---------------------------------------------------------------------------
// Scratch (device globals — no runtime allocation allowed)
// ---------------------------------------------------------------------------
__device__ float  g_P[(size_t)S_N * F2];
__device__ float  g_aggH[(size_t)T_N * F2];
__device__ float  g_h3[(size_t)T_N * F4];
__device__ float  g_Wmid[(size_t)F2 * F4];
__device__ float  g_bvec[F4];
__device__ float  g_c2[F4];
__device__ int    g_cnt[T_N];
__device__ double g_sum[FDIM];
__device__ double g_sumsq[FDIM];
// Pre-split bf16 weights, transposed to [n][k]
__device__ __align__(16) __nv_bfloat16 g_Bpre_hi[(size_t)F2 * FDIM];
__device__ __align__(16) __nv_bfloat16 g_Bpre_lo[(size_t)F2 * FDIM];
__device__ __align__(16) __nv_bfloat16 g_Bedge_hi[(size_t)F2 * FDIM];
__device__ __align__(16) __nv_bfloat16 g_Bedge_lo[(size_t)F2 * FDIM];
__device__ __align__(16) __nv_bfloat16 g_Bn1_hi[(size_t)F4 * 384];
__device__ __align__(16) __nv_bfloat16 g_Bn1_lo[(size_t)F4 * 384];
__device__ __align__(16) __nv_bfloat16 g_Bn2_hi[(size_t)FDIM * F4];
__device__ __align__(16) __nv_bfloat16 g_Bn2_lo[(size_t)FDIM * F4];

// ---------------------------------------------------------------------------
// Helpers
// ---------------------------------------------------------------------------
__device__ __forceinline__ unsigned smem_u32(const void* p) {
    unsigned a;
    asm("{ .reg .u64 t; cvta.to.shared.u64 t, %1; cvt.u32.u64 %0, t; }"
        : "=r"(a) : "l"(p));
    return a;
}
__device__ __forceinline__ void ldsm4(unsigned& r0, unsigned& r1, unsigned& r2,
                                      unsigned& r3, unsigned addr) {
    asm volatile("ldmatrix.sync.aligned.m8n8.x4.shared.b16 {%0,%1,%2,%3}, [%4];"
                 : "=r"(r0), "=r"(r1), "=r"(r2), "=r"(r3) : "r"(addr));
}
__device__ __forceinline__ void mma16816(float* c, const unsigned* a, const unsigned* b) {
    asm volatile(
        "mma.sync.aligned.m16n8k16.row.col.f32.bf16.bf16.f32 "
        "{%0,%1,%2,%3}, {%4,%5,%6,%7}, {%8,%9}, {%0,%1,%2,%3};"
        : "+f"(c[0]), "+f"(c[1]), "+f"(c[2]), "+f"(c[3])
        : "r"(a[0]), "r"(a[1]), "r"(a[2]), "r"(a[3]), "r"(b[0]), "r"(b[1]));
}
__device__ __forceinline__ void split_store(__nv_bfloat16* ph, __nv_bfloat16* pl, float2 v) {
    __nv_bfloat16 hx = __float2bfloat16_rn(v.x);
    __nv_bfloat16 hy = __float2bfloat16_rn(v.y);
    __nv_bfloat16 lx = __float2bfloat16_rn(v.x - __bfloat162float(hx));
    __nv_bfloat16 ly = __float2bfloat16_rn(v.y - __bfloat162float(hy));
    __nv_bfloat162 h; h.x = hx; h.y = hy;
    __nv_bfloat162 l; l.x = lx; l.y = ly;
    *reinterpret_cast<__nv_bfloat162*>(ph) = h;
    *reinterpret_cast<__nv_bfloat162*>(pl) = l;
}

// One K=16 chunk of warp-level split-bf16 MMAs.
// acc layout: acc[mi*2NT + ni][4]
template<int NT>
__device__ __forceinline__ void mma_chunk_t(unsigned aH, unsigned aL,
                                            unsigned bHa, unsigned bLa,
                                            float (*acc)[4]) {
    unsigned ah[2][4], al[2][4];
    ldsm4(ah[0][0], ah[0][1], ah[0][2], ah[0][3], aH);
    ldsm4(ah[1][0], ah[1][1], ah[1][2], ah[1][3], aH + 16 * PA * 2);
    ldsm4(al[0][0], al[0][1], al[0][2], al[0][3], aL);
    ldsm4(al[1][0], al[1][1], al[1][2], al[1][3], aL + 16 * PA * 2);
    #pragma unroll
    for (int p2 = 0; p2 < NT; p2++) {
        unsigned bh[4], bl[4];
        ldsm4(bh[0], bh[1], bh[2], bh[3], bHa + p2 * (16 * PA * 2));
        ldsm4(bl[0], bl[1], bl[2], bl[3], bLa + p2 * (16 * PA * 2));
        #pragma unroll
        for (int mi = 0; mi < 2; mi++)
            #pragma unroll
            for (int t = 0; t < 2; t++) {
                float* c = acc[mi * (2 * NT) + 2 * p2 + t];
                mma16816(c, ah[mi], &bh[2 * t]);
                mma16816(c, ah[mi], &bl[2 * t]);
                mma16816(c, al[mi], &bh[2 * t]);
            }
    }
}

// Warp layout 2m x 4n; per-lane ldmatrix base addresses
#define MAKE_ADDRS(NTv)                                                          \
    int lane = threadIdx.x & 31;                                                 \
    int warp = threadIdx.x >> 5;                                                 \
    int wm0 = (warp >> 2) * 32;                                                  \
    int wn0 = (warp & 3) * ((NTv) * 16);                                         \
    unsigned aH = smem_u32(sAh) +                                                \
        ((wm0 + ((lane >> 3) & 1) * 8 + (lane & 7)) * PA + (lane >> 4) * 8) * 2; \
    unsigned aL = smem_u32(sAl) +                                                \
        ((wm0 + ((lane >> 3) & 1) * 8 + (lane & 7)) * PA + (lane >> 4) * 8) * 2; \
    unsigned bHa = smem_u32(sBh) +                                               \
        ((wn0 + (lane >> 4) * 8 + (lane & 7)) * PA + ((lane >> 3) & 1) * 8) * 2; \
    unsigned bLa = smem_u32(sBl) +                                               \
        ((wn0 + (lane >> 4) * 8 + (lane & 7)) * PA + ((lane >> 3) & 1) * 8) * 2;

// B chunk loader: TBN_ rows x 16 cols from pre-split [n][K] global
#define LOAD_B(Bhi, Blo, K, TBN_)                                               \
    for (int p = threadIdx.x; p < (TBN_) * 2; p += 256) {                       \
        int n = p >> 1, j = p & 1;                                              \
        *reinterpret_cast<uint4*>(&sBh[n * PA + 8 * j]) =                       \
            *reinterpret_cast<const uint4*>(&Bhi[(size_t)(n0 + n) * (K) + kt + 8 * j]); \
        *reinterpret_cast<uint4*>(&sBl[n * PA + 8 * j]) =                       \
            *reinterpret_cast<const uint4*>(&Blo[(size_t)(n0 + n) * (K) + kt + 8 * j]); \
    }

// ---------------------------------------------------------------------------
__global__ void zero_kernel() {
    int idx = blockIdx.x * blockDim.x + threadIdx.x;
    int stride = gridDim.x * blockDim.x;
    for (size_t i = idx; i < (size_t)T_N * F2; i += stride) g_aggH[i] = 0.f;
    for (int i = idx; i < T_N; i += stride) g_cnt[i] = 0;
    if (idx < FDIM) { g_sum[idx] = 0.0; g_sumsq[idx] = 0.0; }
}

__global__ void __launch_bounds__(512) compute_Wmid(
    const float* __restrict__ W1b, const float* __restrict__ W2a)
{
    __shared__ float sRow[F2];
    int k = blockIdx.x;
    int j = threadIdx.x;
    if (j < F2) sRow[j] = W1b[(size_t)k * F2 + j];
    __syncthreads();
    float acc = 0.f;
    #pragma unroll 4
    for (int m = 0; m < F2; m++)
        acc = fmaf(sRow[m], W2a[(size_t)(128 + m) * F4 + j], acc);
    g_Wmid[(size_t)k * F4 + j] = acc;
}

__global__ void __launch_bounds__(512) compute_vecs(
    const float* __restrict__ b1b, const float* __restrict__ u,
    const float* __restrict__ W2a, const float* __restrict__ b2a)
{
    int j = threadIdx.x;
    float bv = 0.f;
    for (int m = 0; m < F2; m++)
        bv = fmaf(b1b[m], W2a[(size_t)(128 + m) * F4 + j], bv);
    g_bvec[j] = bv;
    float cv = b2a[j];
    for (int k = 0; k < FDIM; k++)
        cv = fmaf(u[k], W2a[(size_t)(384 + k) * F4 + j], cv);
    g_c2[j] = cv;
}

__device__ __forceinline__ void split1(__nv_bfloat16* ph, __nv_bfloat16* pl, float v) {
    __nv_bfloat16 h = __float2bfloat16_rn(v);
    *ph = h;
    *pl = __float2bfloat16_rn(v - __bfloat162float(h));
}
__global__ void convert_Bpre(const float* __restrict__ W1a) {
    int idx = blockIdx.x * blockDim.x + threadIdx.x;
    if (idx >= F2 * FDIM) return;
    int n = idx >> 7, k = idx & 127;
    split1(&g_Bpre_hi[idx], &g_Bpre_lo[idx], W1a[(size_t)k * F2 + n]);
}
__global__ void convert_Bedge(const float* __restrict__ W1a) {
    int idx = blockIdx.x * blockDim.x + threadIdx.x;
    if (idx >= F2 * FDIM) return;
    int n = idx >> 7, k = idx & 127;
    split1(&g_Bedge_hi[idx], &g_Bedge_lo[idx], W1a[(size_t)(FDIM + k) * F2 + n]);
}
__global__ void convert_Bn1(const float* __restrict__ W2a) {
    int idx = blockIdx.x * blockDim.x + threadIdx.x;
    if (idx >= F4 * 384) return;
    int n = idx / 384, k = idx % 384;
    float v = (k < FDIM) ? W2a[(size_t)k * F4 + n] : g_Wmid[(size_t)(k - FDIM) * F4 + n];
    split1(&g_Bn1_hi[idx], &g_Bn1_lo[idx], v);
}
__global__ void convert_Bn2(const float* __restrict__ W2b) {
    int idx = blockIdx.x * blockDim.x + threadIdx.x;
    if (idx >= FDIM * F4) return;
    int n = idx >> 9, k = idx & 511;
    split1(&g_Bn2_hi[idx], &g_Bn2_lo[idx], W2b[(size_t)k * FDIM + n]);
}

// ---------------------------------------------------------------------------
// GEMM pre: x_s[S,128] @ Bpre^T -> g_P (+ b1a).  Full N=256 per CTA.
// ---------------------------------------------------------------------------
__global__ void __launch_bounds__(256) gemm_pre(
    const float* __restrict__ x_s, const float* __restrict__ b1a)
{
    __shared__ __align__(16) __nv_bfloat16 sAh[TBM * PA], sAl[TBM * PA];
    __shared__ __align__(16) __nv_bfloat16 sBh[F2 * PA], sBl[F2 * PA];
    int m0 = blockIdx.x * TBM;
    const int n0 = 0;
    float acc[16][4] = {};
    MAKE_ADDRS(4);

    for (int kt = 0; kt < FDIM; kt += TBK) {
        #pragma unroll
        for (int it = 0; it < 2; it++) {
            int p = threadIdx.x + it * 256;
            int row = p >> 3, cp = p & 7;
            int gm = m0 + row;
            float2 v = make_float2(0.f, 0.f);
            if (gm < S_N)
                v = *reinterpret_cast<const float2*>(x_s + (size_t)gm * FDIM + kt + 2 * cp);
            split_store(&sAh[row * PA + 2 * cp], &sAl[row * PA + 2 * cp], v);
        }
        LOAD_B(g_Bpre_hi, g_Bpre_lo, FDIM, F2);
        __syncthreads();
        mma_chunk_t<4>(aH, aL, bHa, bLa, acc);
        __syncthreads();
    }

    #pragma unroll
    for (int mi = 0; mi < 2; mi++)
        #pragma unroll
        for (int h = 0; h < 2; h++) {
            int gm = m0 + wm0 + mi * 16 + (lane >> 2) + h * 8;
            if (gm >= S_N) continue;
            #pragma unroll
            for (int ni = 0; ni < 8; ni++) {
                int col = wn0 + ni * 8 + 2 * (lane & 3);
                float2 bb = *reinterpret_cast<const float2*>(b1a + col);
                float2 o;
                o.x = acc[mi * 8 + ni][h * 2 + 0] + bb.x;
                o.y = acc[mi * 8 + ni][h * 2 + 1] + bb.y;
                *reinterpret_cast<float2*>(&g_P[(size_t)gm * F2 + col]) = o;
            }
        }
}

// ---------------------------------------------------------------------------
// GEMM edge: edge_attr[E,128] @ Bedge^T; epi leaky(D+P[src]) atomic -> aggH
// Full N=256 per CTA, 1-D grid; cnt counted once here.
// ---------------------------------------------------------------------------
__global__ void __launch_bounds__(256) gemm_edge(
    const float* __restrict__ edge_attr, const int* __restrict__ eidx)
{
    __shared__ __align__(16) __nv_bfloat16 sAh[TBM * PA], sAl[TBM * PA];
    __shared__ __align__(16) __nv_bfloat16 sBh[F2 * PA], sBl[F2 * PA];
    __shared__ int sSrc[TBM], sTgt[TBM];
    int m0 = blockIdx.x * TBM;     // E_N divisible by 64
    const int n0 = 0;

    if (threadIdx.x < TBM) {
        int m = m0 + threadIdx.x;
        int sv = eidx[m];
        int tv = eidx[E_N + m];
        atomicAdd(&g_cnt[tv], 1);
        sSrc[threadIdx.x] = sv;
        sTgt[threadIdx.x] = tv;
    }

    float acc[16][4] = {};
    MAKE_ADDRS(4);

    for (int kt = 0; kt < FDIM; kt += TBK) {
        #pragma unroll
        for (int it = 0; it < 2; it++) {
            int p = threadIdx.x + it * 256;
            int row = p >> 3, cp = p & 7;
            float2 v = *reinterpret_cast<const float2*>(
                edge_attr + (size_t)(m0 + row) * FDIM + kt + 2 * cp);
            split_store(&sAh[row * PA + 2 * cp], &sAl[row * PA + 2 * cp], v);
        }
        LOAD_B(g_Bedge_hi, g_Bedge_lo, FDIM, F2);
        __syncthreads();
        mma_chunk_t<4>(aH, aL, bHa, bLa, acc);
        __syncthreads();
    }

    #pragma unroll
    for (int mi = 0; mi < 2; mi++)
        #pragma unroll
        for (int h = 0; h < 2; h++) {
            int r = wm0 + mi * 16 + (lane >> 2) + h * 8;
            int s = sSrc[r], t = sTgt[r];
            #pragma unroll
            for (int ni = 0; ni < 8; ni++) {
                int col = wn0 + ni * 8 + 2 * (lane & 3);
                float2 pv = *reinterpret_cast<const float2*>(&g_P[(size_t)s * F2 + col]);
                float v0 = acc[mi * 8 + ni][h * 2 + 0] + pv.x;
                float v1 = acc[mi * 8 + ni][h * 2 + 1] + pv.y;
                v0 = v0 >= 0.f ? v0 : SLOPE * v0;
                v1 = v1 >= 0.f ? v1 : SLOPE * v1;
                atomicAdd(&g_aggH[(size_t)t * F2 + col], v0);
                atomicAdd(&g_aggH[(size_t)t * F2 + col + 1], v1);
            }
        }
}

// ---------------------------------------------------------------------------
// GEMM node1: [x_t | aggH][T,384] @ Bn1^T; epi leaky(+c2+cnt*bvec) -> g_h3
// Two N-blocks of 256.
// ---------------------------------------------------------------------------
__global__ void __launch_bounds__(256) gemm_node1(const float* __restrict__ x_t)
{
    __shared__ __align__(16) __nv_bfloat16 sAh[TBM * PA], sAl[TBM * PA];
    __shared__ __align__(16) __nv_bfloat16 sBh[F2 * PA], sBl[F2 * PA];
    int m0 = blockIdx.y * TBM;
    int n0 = blockIdx.x * F2;
    float acc[16][4] = {};
    MAKE_ADDRS(4);

    for (int kt = 0; kt < 384; kt += TBK) {
        #pragma unroll
        for (int it = 0; it < 2; it++) {
            int p = threadIdx.x + it * 256;
            int row = p >> 3, cp = p & 7;
            int gm = m0 + row;
            int gk = kt + 2 * cp;
            float2 v = make_float2(0.f, 0.f);
            if (gm < T_N) {
                if (gk < FDIM)
                    v = *reinterpret_cast<const float2*>(x_t + (size_t)gm * FDIM + gk);
                else
                    v = *reinterpret_cast<const float2*>(&g_aggH[(size_t)gm * F2 + gk - FDIM]);
            }
            split_store(&sAh[row * PA + 2 * cp], &sAl[row * PA + 2 * cp], v);
        }
        LOAD_B(g_Bn1_hi, g_Bn1_lo, 384, F2);
        __syncthreads();
        mma_chunk_t<4>(aH, aL, bHa, bLa, acc);
        __syncthreads();
    }

    #pragma unroll
    for (int mi = 0; mi < 2; mi++)
        #pragma unroll
        for (int h = 0; h < 2; h++) {
            int gm = m0 + wm0 + mi * 16 + (lane >> 2) + h * 8;
            if (gm >= T_N) continue;
            float c = (float)g_cnt[gm];
            #pragma unroll
            for (int ni = 0; ni < 8; ni++) {
                int col = n0 + wn0 + ni * 8 + 2 * (lane & 3);
                float2 c2v = *reinterpret_cast<const float2*>(&g_c2[col]);
                float2 bvv = *reinterpret_cast<const float2*>(&g_bvec[col]);
                float v0 = acc[mi * 8 + ni][h * 2 + 0] + c2v.x + c * bvv.x;
                float v1 = acc[mi * 8 + ni][h * 2 + 1] + c2v.y + c * bvv.y;
                v0 = v0 >= 0.f ? v0 : SLOPE * v0;
                v1 = v1 >= 0.f ? v1 : SLOPE * v1;
                float2 o; o.x = v0; o.y = v1;
                *reinterpret_cast<float2*>(&g_h3[(size_t)gm * F4 + col]) = o;
            }
        }
}

// ---------------------------------------------------------------------------
// GEMM node2: g_h3[T,512] @ Bn2^T (+b2b) -> out.  Full N=128 per CTA (NT=2).
// ---------------------------------------------------------------------------
__global__ void __launch_bounds__(256) gemm_node2(
    const float* __restrict__ b2b, float* __restrict__ out)
{
    __shared__ __align__(16) __nv_bfloat16 sAh[TBM * PA], sAl[TBM * PA];
    __shared__ __align__(16) __nv_bfloat16 sBh[FDIM * PA], sBl[FDIM * PA];
    int m0 = blockIdx.x * TBM;
    const int n0 = 0;
    float acc[8][4] = {};
    MAKE_ADDRS(2);

    for (int kt = 0; kt < F4; kt += TBK) {
        #pragma unroll
        for (int it = 0; it < 2; it++) {
            int p = threadIdx.x + it * 256;
            int row = p >> 3, cp = p & 7;
            int gm = m0 + row;
            float2 v = make_float2(0.f, 0.f);
            if (gm < T_N)
                v = *reinterpret_cast<const float2*>(&g_h3[(size_t)gm * F4 + kt + 2 * cp]);
            split_store(&sAh[row * PA + 2 * cp], &sAl[row * PA + 2 * cp], v);
        }
        LOAD_B(g_Bn2_hi, g_Bn2_lo, F4, FDIM);
        __syncthreads();
        mma_chunk_t<2>(aH, aL, bHa, bLa, acc);
        __syncthreads();
    }

    #pragma unroll
    for (int mi = 0; mi < 2; mi++)
        #pragma unroll
        for (int h = 0; h < 2; h++) {
            int gm = m0 + wm0 + mi * 16 + (lane >> 2) + h * 8;
            if (gm >= T_N) continue;
            #pragma unroll
            for (int ni = 0; ni < 4; ni++) {
                int col = wn0 + ni * 8 + 2 * (lane & 3);
                float2 bb = *reinterpret_cast<const float2*>(b2b + col);
                float2 o;
                o.x = acc[mi * 4 + ni][h * 2 + 0] + bb.x;
                o.y = acc[mi * 4 + ni][h * 2 + 1] + bb.y;
                *reinterpret_cast<float2*>(&out[(size_t)gm * FDIM + col]) = o;
            }
        }
}

// ---------------------------------------------------------------------------
// BatchNorm
// ---------------------------------------------------------------------------
__global__ void bn_stats(const float* __restrict__ y) {
    int c = threadIdx.x & (FDIM - 1);
    int half = threadIdx.x >> 7;
    double s = 0.0, sq = 0.0;
    for (int m = blockIdx.x * 2 + half; m < T_N; m += gridDim.x * 2) {
        float v = y[(size_t)m * FDIM + c];
        s += v;
        sq += (double)v * (double)v;
    }
    atomicAdd(&g_sum[c], s);
    atomicAdd(&g_sumsq[c], sq);
}

__global__ void bn_norm(float* __restrict__ y,
                        const float* __restrict__ gamma,
                        const float* __restrict__ beta) {
    size_t idx = (size_t)blockIdx.x * blockDim.x + threadIdx.x;
    if (idx >= (size_t)T_N * FDIM) return;
    int c = (int)(idx & (FDIM - 1));
    double mean = g_sum[c] / (double)T_N;
    double var = g_sumsq[c] / (double)T_N - mean * mean;
    float scale = rsqrtf((float)var + BN_EPS) * gamma[c];
    y[idx] = (float)((double)y[idx] - mean) * scale + beta[c];
}

extern "C" void kernel_launch(void* const* d_in, const int* in_sizes, int n_in,
                              void* d_out, int out_size) {
    const float* x_s       = (const float*)d_in[0];
    const float* x_t       = (const float*)d_in[1];
    const float* edge_attr = (const float*)d_in[2];
    const float* u         = (const float*)d_in[3];
    const int*   eidx      = (const int*)d_in[4];
    const float* W1a       = (const float*)d_in[5];
    const float* b1a       = (const float*)d_in[6];
    const float* W1b       = (const float*)d_in[7];
    const float* b1b       = (const float*)d_in[8];
    const float* W2a       = (const float*)d_in[9];
    const float* b2a       = (const float*)d_in[10];
    const float* W2b       = (const float*)d_in[11];
    const float* b2b       = (const float*)d_in[12];
    const float* gamma     = (const float*)d_in[13];
    const float* beta      = (const float*)d_in[14];
    float* out = (float*)d_out;

    zero_kernel<<<1024, 256>>>();
    compute_Wmid<<<F2, 512>>>(W1b, W2a);
    compute_vecs<<<1, 512>>>(b1b, u, W2a, b2a);
    convert_Bpre<<<(F2 * FDIM + 255) / 256, 256>>>(W1a);
    convert_Bedge<<<(F2 * FDIM + 255) / 256, 256>>>(W1a);
    convert_Bn1<<<(F4 * 384 + 255) / 256, 256>>>(W2a);
    convert_Bn2<<<(FDIM * F4 + 255) / 256, 256>>>(W2b);

    int mblk = (S_N + TBM - 1) / TBM;               // 782
    gemm_pre<<<mblk, 256>>>(x_s, b1a);

    gemm_edge<<<E_N / TBM, 256>>>(edge_attr, eidx); // 9375

    dim3 gN1(2, mblk);
    gemm_node1<<<gN1, 256>>>(x_t);

    gemm_node2<<<mblk, 256>>>(b2b, out);

    bn_stats<<<512, 256>>>(out);
    bn_norm<<<(T_N * FDIM + 255) / 256, 256>>>(out, gamma, beta);
}

// round 11
// speedup vs baseline: 3.0700x; 1.0572x over previous
#include <cuda_runtime.h>
#include <cuda_bf16.h>
#include <cstdint>

#define FDIM 128
#define S_N 50000
#define T_N 50000
#define E_N 600000
#define F2 256
#define F4 512
#define SLOPE 0.1f
#define BN_EPS 1e-5f

#define PA 24          // smem pitch (48B rows: 16B-aligned, conflict-free ldmatrix)
#define TBM 64         // CTA tile M (non-edge kernels)
#define TBME 128       // CTA tile M (edge kernel, 512 threads)
#define TBK 16         // K chunk (one k16 step)

// ---------------------------------------------------------------------------
// Scratch (device globals — no runtime allocation allowed)
// ---------------------------------------------------------------------------
__device__ float  g_P[(size_t)S_N * F2];
__device__ float  g_aggH[(size_t)T_N * F2];
__device__ float  g_h3[(size_t)T_N * F4];
__device__ float  g_Wmid[(size_t)F2 * F4];
__device__ float  g_bvec[F4];
__device__ float  g_c2[F4];
__device__ int    g_cnt[T_N];
__device__ double g_sum[FDIM];
__device__ double g_sumsq[FDIM];
// Pre-split bf16 weights, transposed to [n][k]
__device__ __align__(16) __nv_bfloat16 g_Bpre_hi[(size_t)F2 * FDIM];
__device__ __align__(16) __nv_bfloat16 g_Bpre_lo[(size_t)F2 * FDIM];
__device__ __align__(16) __nv_bfloat16 g_Bedge_hi[(size_t)F2 * FDIM];
__device__ __align__(16) __nv_bfloat16 g_Bedge_lo[(size_t)F2 * FDIM];
__device__ __align__(16) __nv_bfloat16 g_Bn1_hi[(size_t)F4 * 384];
__device__ __align__(16) __nv_bfloat16 g_Bn1_lo[(size_t)F4 * 384];
__device__ __align__(16) __nv_bfloat16 g_Bn2_hi[(size_t)FDIM * F4];
__device__ __align__(16) __nv_bfloat16 g_Bn2_lo[(size_t)FDIM * F4];

// ---------------------------------------------------------------------------
// Helpers
// ---------------------------------------------------------------------------
__device__ __forceinline__ unsigned smem_u32(const void* p) {
    unsigned a;
    asm("{ .reg .u64 t; cvta.to.shared.u64 t, %1; cvt.u32.u64 %0, t; }"
        : "=r"(a) : "l"(p));
    return a;
}
__device__ __forceinline__ void ldsm4(unsigned& r0, unsigned& r1, unsigned& r2,
                                      unsigned& r3, unsigned addr) {
    asm volatile("ldmatrix.sync.aligned.m8n8.x4.shared.b16 {%0,%1,%2,%3}, [%4];"
                 : "=r"(r0), "=r"(r1), "=r"(r2), "=r"(r3) : "r"(addr));
}
__device__ __forceinline__ void mma16816(float* c, const unsigned* a, const unsigned* b) {
    asm volatile(
        "mma.sync.aligned.m16n8k16.row.col.f32.bf16.bf16.f32 "
        "{%0,%1,%2,%3}, {%4,%5,%6,%7}, {%8,%9}, {%0,%1,%2,%3};"
        : "+f"(c[0]), "+f"(c[1]), "+f"(c[2]), "+f"(c[3])
        : "r"(a[0]), "r"(a[1]), "r"(a[2]), "r"(a[3]), "r"(b[0]), "r"(b[1]));
}
__device__ __forceinline__ void red_add_v2(float* p, float a, float b) {
    asm volatile("red.global.add.v2.f32 [%0], {%1, %2};"
                 :: "l"(p), "f"(a), "f"(b) : "memory");
}
__device__ __forceinline__ void split_store(__nv_bfloat16* ph, __nv_bfloat16* pl, float2 v) {
    __nv_bfloat16 hx = __float2bfloat16_rn(v.x);
    __nv_bfloat16 hy = __float2bfloat16_rn(v.y);
    __nv_bfloat16 lx = __float2bfloat16_rn(v.x - __bfloat162float(hx));
    __nv_bfloat16 ly = __float2bfloat16_rn(v.y - __bfloat162float(hy));
    __nv_bfloat162 h; h.x = hx; h.y = hy;
    __nv_bfloat162 l; l.x = lx; l.y = ly;
    *reinterpret_cast<__nv_bfloat162*>(ph) = h;
    *reinterpret_cast<__nv_bfloat162*>(pl) = l;
}

// One K=16 chunk of warp-level split-bf16 MMAs.  acc[mi*2NT + ni][4]
template<int NT>
__device__ __forceinline__ void mma_chunk_t(unsigned aH, unsigned aL,
                                            unsigned bHa, unsigned bLa,
                                            float (*acc)[4]) {
    unsigned ah[2][4], al[2][4];
    ldsm4(ah[0][0], ah[0][1], ah[0][2], ah[0][3], aH);
    ldsm4(ah[1][0], ah[1][1], ah[1][2], ah[1][3], aH + 16 * PA * 2);
    ldsm4(al[0][0], al[0][1], al[0][2], al[0][3], aL);
    ldsm4(al[1][0], al[1][1], al[1][2], al[1][3], aL + 16 * PA * 2);
    #pragma unroll
    for (int p2 = 0; p2 < NT; p2++) {
        unsigned bh[4], bl[4];
        ldsm4(bh[0], bh[1], bh[2], bh[3], bHa + p2 * (16 * PA * 2));
        ldsm4(bl[0], bl[1], bl[2], bl[3], bLa + p2 * (16 * PA * 2));
        #pragma unroll
        for (int mi = 0; mi < 2; mi++)
            #pragma unroll
            for (int t = 0; t < 2; t++) {
                float* c = acc[mi * (2 * NT) + 2 * p2 + t];
                mma16816(c, ah[mi], &bh[2 * t]);
                mma16816(c, ah[mi], &bl[2 * t]);
                mma16816(c, al[mi], &bh[2 * t]);
            }
    }
}

// Warp layout: warps (warp>>2) m-tiles of 32, (warp&3) n-blocks of NT*16
#define MAKE_ADDRS(NTv)                                                          \
    int lane = threadIdx.x & 31;                                                 \
    int warp = threadIdx.x >> 5;                                                 \
    int wm0 = (warp >> 2) * 32;                                                  \
    int wn0 = (warp & 3) * ((NTv) * 16);                                         \
    unsigned aH = smem_u32(sAh) +                                                \
        ((wm0 + ((lane >> 3) & 1) * 8 + (lane & 7)) * PA + (lane >> 4) * 8) * 2; \
    unsigned aL = smem_u32(sAl) +                                                \
        ((wm0 + ((lane >> 3) & 1) * 8 + (lane & 7)) * PA + (lane >> 4) * 8) * 2; \
    unsigned bHa = smem_u32(sBh) +                                               \
        ((wn0 + (lane >> 4) * 8 + (lane & 7)) * PA + ((lane >> 3) & 1) * 8) * 2; \
    unsigned bLa = smem_u32(sBl) +                                               \
        ((wn0 + (lane >> 4) * 8 + (lane & 7)) * PA + ((lane >> 3) & 1) * 8) * 2;

// B chunk loader: TBN_ rows x 16 cols from pre-split [n][K] global (NTHR threads)
#define LOAD_B(Bhi, Blo, K, TBN_, NTHR)                                         \
    for (int p = threadIdx.x; p < (TBN_) * 2; p += (NTHR)) {                    \
        int n = p >> 1, j = p & 1;                                              \
        *reinterpret_cast<uint4*>(&sBh[n * PA + 8 * j]) =                       \
            *reinterpret_cast<const uint4*>(&Bhi[(size_t)(n0 + n) * (K) + kt + 8 * j]); \
        *reinterpret_cast<uint4*>(&sBl[n * PA + 8 * j]) =                       \
            *reinterpret_cast<const uint4*>(&Blo[(size_t)(n0 + n) * (K) + kt + 8 * j]); \
    }

// ---------------------------------------------------------------------------
__global__ void zero_kernel() {
    int idx = blockIdx.x * blockDim.x + threadIdx.x;
    int stride = gridDim.x * blockDim.x;
    float4* a4 = reinterpret_cast<float4*>(g_aggH);
    const float4 z = make_float4(0.f, 0.f, 0.f, 0.f);
    for (size_t i = idx; i < (size_t)T_N * F2 / 4; i += stride) a4[i] = z;
    for (int i = idx; i < T_N; i += stride) g_cnt[i] = 0;
    if (idx < FDIM) { g_sum[idx] = 0.0; g_sumsq[idx] = 0.0; }
}

__global__ void __launch_bounds__(512) compute_Wmid(
    const float* __restrict__ W1b, const float* __restrict__ W2a)
{
    __shared__ float sRow[F2];
    int k = blockIdx.x;
    int j = threadIdx.x;
    if (j < F2) sRow[j] = W1b[(size_t)k * F2 + j];
    __syncthreads();
    float acc = 0.f;
    #pragma unroll 4
    for (int m = 0; m < F2; m++)
        acc = fmaf(sRow[m], W2a[(size_t)(128 + m) * F4 + j], acc);
    g_Wmid[(size_t)k * F4 + j] = acc;
}

__global__ void __launch_bounds__(512) compute_vecs(
    const float* __restrict__ b1b, const float* __restrict__ u,
    const float* __restrict__ W2a, const float* __restrict__ b2a)
{
    int j = threadIdx.x;
    float bv = 0.f;
    for (int m = 0; m < F2; m++)
        bv = fmaf(b1b[m], W2a[(size_t)(128 + m) * F4 + j], bv);
    g_bvec[j] = bv;
    float cv = b2a[j];
    for (int k = 0; k < FDIM; k++)
        cv = fmaf(u[k], W2a[(size_t)(384 + k) * F4 + j], cv);
    g_c2[j] = cv;
}

__device__ __forceinline__ void split1(__nv_bfloat16* ph, __nv_bfloat16* pl, float v) {
    __nv_bfloat16 h = __float2bfloat16_rn(v);
    *ph = h;
    *pl = __float2bfloat16_rn(v - __bfloat162float(h));
}
__global__ void convert_Bpre(const float* __restrict__ W1a) {
    int idx = blockIdx.x * blockDim.x + threadIdx.x;
    if (idx >= F2 * FDIM) return;
    int n = idx >> 7, k = idx & 127;
    split1(&g_Bpre_hi[idx], &g_Bpre_lo[idx], W1a[(size_t)k * F2 + n]);
}
__global__ void convert_Bedge(const float* __restrict__ W1a) {
    int idx = blockIdx.x * blockDim.x + threadIdx.x;
    if (idx >= F2 * FDIM) return;
    int n = idx >> 7, k = idx & 127;
    split1(&g_Bedge_hi[idx], &g_Bedge_lo[idx], W1a[(size_t)(FDIM + k) * F2 + n]);
}
__global__ void convert_Bn1(const float* __restrict__ W2a) {
    int idx = blockIdx.x * blockDim.x + threadIdx.x;
    if (idx >= F4 * 384) return;
    int n = idx / 384, k = idx % 384;
    float v = (k < FDIM) ? W2a[(size_t)k * F4 + n] : g_Wmid[(size_t)(k - FDIM) * F4 + n];
    split1(&g_Bn1_hi[idx], &g_Bn1_lo[idx], v);
}
__global__ void convert_Bn2(const float* __restrict__ W2b) {
    int idx = blockIdx.x * blockDim.x + threadIdx.x;
    if (idx >= FDIM * F4) return;
    int n = idx >> 9, k = idx & 511;
    split1(&g_Bn2_hi[idx], &g_Bn2_lo[idx], W2b[(size_t)k * FDIM + n]);
}

// ---------------------------------------------------------------------------
// GEMM pre: x_s[S,128] @ Bpre^T -> g_P (+ b1a).  Full N=256 per CTA.
// ---------------------------------------------------------------------------
__global__ void __launch_bounds__(256) gemm_pre(
    const float* __restrict__ x_s, const float* __restrict__ b1a)
{
    __shared__ __align__(16) __nv_bfloat16 sAh[TBM * PA], sAl[TBM * PA];
    __shared__ __align__(16) __nv_bfloat16 sBh[F2 * PA], sBl[F2 * PA];
    int m0 = blockIdx.x * TBM;
    const int n0 = 0;
    float acc[16][4] = {};
    MAKE_ADDRS(4);

    for (int kt = 0; kt < FDIM; kt += TBK) {
        #pragma unroll
        for (int it = 0; it < 2; it++) {
            int p = threadIdx.x + it * 256;
            int row = p >> 3, cp = p & 7;
            int gm = m0 + row;
            float2 v = make_float2(0.f, 0.f);
            if (gm < S_N)
                v = *reinterpret_cast<const float2*>(x_s + (size_t)gm * FDIM + kt + 2 * cp);
            split_store(&sAh[row * PA + 2 * cp], &sAl[row * PA + 2 * cp], v);
        }
        LOAD_B(g_Bpre_hi, g_Bpre_lo, FDIM, F2, 256);
        __syncthreads();
        mma_chunk_t<4>(aH, aL, bHa, bLa, acc);
        __syncthreads();
    }

    #pragma unroll
    for (int mi = 0; mi < 2; mi++)
        #pragma unroll
        for (int h = 0; h < 2; h++) {
            int gm = m0 + wm0 + mi * 16 + (lane >> 2) + h * 8;
            if (gm >= S_N) continue;
            #pragma unroll
            for (int ni = 0; ni < 8; ni++) {
                int col = wn0 + ni * 8 + 2 * (lane & 3);
                float2 bb = *reinterpret_cast<const float2*>(b1a + col);
                float2 o;
                o.x = acc[mi * 8 + ni][h * 2 + 0] + bb.x;
                o.y = acc[mi * 8 + ni][h * 2 + 1] + bb.y;
                *reinterpret_cast<float2*>(&g_P[(size_t)gm * F2 + col]) = o;
            }
        }
}

// ---------------------------------------------------------------------------
// GEMM edge: edge_attr[E,128] @ Bedge^T; epi leaky(D+P[src]) red.v2 -> aggH
// TBM=128, 512 threads, full N=256 per CTA.
// ---------------------------------------------------------------------------
__global__ void __launch_bounds__(512) gemm_edge(
    const float* __restrict__ edge_attr, const int* __restrict__ eidx)
{
    __shared__ __align__(16) __nv_bfloat16 sAh[TBME * PA], sAl[TBME * PA];
    __shared__ __align__(16) __nv_bfloat16 sBh[F2 * PA], sBl[F2 * PA];
    __shared__ int sSrc[TBME], sTgt[TBME];
    int m0 = blockIdx.x * TBME;
    const int n0 = 0;

    if (threadIdx.x < TBME) {
        int m = m0 + threadIdx.x;
        int sv = 0, tv = 0;
        if (m < E_N) {
            sv = eidx[m];
            tv = eidx[E_N + m];
            atomicAdd(&g_cnt[tv], 1);
        }
        sSrc[threadIdx.x] = sv;
        sTgt[threadIdx.x] = tv;
    }

    float acc[16][4] = {};
    MAKE_ADDRS(4);

    for (int kt = 0; kt < FDIM; kt += TBK) {
        #pragma unroll
        for (int it = 0; it < 2; it++) {
            int p = threadIdx.x + it * 512;
            int row = p >> 3, cp = p & 7;
            int gm = m0 + row;
            float2 v = make_float2(0.f, 0.f);
            if (gm < E_N)
                v = *reinterpret_cast<const float2*>(
                        edge_attr + (size_t)gm * FDIM + kt + 2 * cp);
            split_store(&sAh[row * PA + 2 * cp], &sAl[row * PA + 2 * cp], v);
        }
        LOAD_B(g_Bedge_hi, g_Bedge_lo, FDIM, F2, 512);
        __syncthreads();
        mma_chunk_t<4>(aH, aL, bHa, bLa, acc);
        __syncthreads();
    }

    #pragma unroll
    for (int mi = 0; mi < 2; mi++)
        #pragma unroll
        for (int h = 0; h < 2; h++) {
            int r = wm0 + mi * 16 + (lane >> 2) + h * 8;
            int gm = m0 + r;
            if (gm >= E_N) continue;
            int s = sSrc[r], t = sTgt[r];
            #pragma unroll
            for (int ni = 0; ni < 8; ni++) {
                int col = wn0 + ni * 8 + 2 * (lane & 3);
                float2 pv = *reinterpret_cast<const float2*>(&g_P[(size_t)s * F2 + col]);
                float v0 = acc[mi * 8 + ni][h * 2 + 0] + pv.x;
                float v1 = acc[mi * 8 + ni][h * 2 + 1] + pv.y;
                v0 = v0 >= 0.f ? v0 : SLOPE * v0;
                v1 = v1 >= 0.f ? v1 : SLOPE * v1;
                red_add_v2(&g_aggH[(size_t)t * F2 + col], v0, v1);
            }
        }
}

// ---------------------------------------------------------------------------
// GEMM node1: [x_t | aggH][T,384] @ Bn1^T; epi leaky(+c2+cnt*bvec) -> g_h3
// ---------------------------------------------------------------------------
__global__ void __launch_bounds__(256) gemm_node1(const float* __restrict__ x_t)
{
    __shared__ __align__(16) __nv_bfloat16 sAh[TBM * PA], sAl[TBM * PA];
    __shared__ __align__(16) __nv_bfloat16 sBh[F2 * PA], sBl[F2 * PA];
    int m0 = blockIdx.y * TBM;
    int n0 = blockIdx.x * F2;
    float acc[16][4] = {};
    MAKE_ADDRS(4);

    for (int kt = 0; kt < 384; kt += TBK) {
        #pragma unroll
        for (int it = 0; it < 2; it++) {
            int p = threadIdx.x + it * 256;
            int row = p >> 3, cp = p & 7;
            int gm = m0 + row;
            int gk = kt + 2 * cp;
            float2 v = make_float2(0.f, 0.f);
            if (gm < T_N) {
                if (gk < FDIM)
                    v = *reinterpret_cast<const float2*>(x_t + (size_t)gm * FDIM + gk);
                else
                    v = *reinterpret_cast<const float2*>(&g_aggH[(size_t)gm * F2 + gk - FDIM]);
            }
            split_store(&sAh[row * PA + 2 * cp], &sAl[row * PA + 2 * cp], v);
        }
        LOAD_B(g_Bn1_hi, g_Bn1_lo, 384, F2, 256);
        __syncthreads();
        mma_chunk_t<4>(aH, aL, bHa, bLa, acc);
        __syncthreads();
    }

    #pragma unroll
    for (int mi = 0; mi < 2; mi++)
        #pragma unroll
        for (int h = 0; h < 2; h++) {
            int gm = m0 + wm0 + mi * 16 + (lane >> 2) + h * 8;
            if (gm >= T_N) continue;
            float c = (float)g_cnt[gm];
            #pragma unroll
            for (int ni = 0; ni < 8; ni++) {
                int col = n0 + wn0 + ni * 8 + 2 * (lane & 3);
                float2 c2v = *reinterpret_cast<const float2*>(&g_c2[col]);
                float2 bvv = *reinterpret_cast<const float2*>(&g_bvec[col]);
                float v0 = acc[mi * 8 + ni][h * 2 + 0] + c2v.x + c * bvv.x;
                float v1 = acc[mi * 8 + ni][h * 2 + 1] + c2v.y + c * bvv.y;
                v0 = v0 >= 0.f ? v0 : SLOPE * v0;
                v1 = v1 >= 0.f ? v1 : SLOPE * v1;
                float2 o; o.x = v0; o.y = v1;
                *reinterpret_cast<float2*>(&g_h3[(size_t)gm * F4 + col]) = o;
            }
        }
}

// ---------------------------------------------------------------------------
// GEMM node2: g_h3[T,512] @ Bn2^T (+b2b) -> out.  Full N=128 per CTA (NT=2).
// ---------------------------------------------------------------------------
__global__ void __launch_bounds__(256) gemm_node2(
    const float* __restrict__ b2b, float* __restrict__ out)
{
    __shared__ __align__(16) __nv_bfloat16 sAh[TBM * PA], sAl[TBM * PA];
    __shared__ __align__(16) __nv_bfloat16 sBh[FDIM * PA], sBl[FDIM * PA];
    int m0 = blockIdx.x * TBM;
    const int n0 = 0;
    float acc[8][4] = {};
    MAKE_ADDRS(2);

    for (int kt = 0; kt < F4; kt += TBK) {
        #pragma unroll
        for (int it = 0; it < 2; it++) {
            int p = threadIdx.x + it * 256;
            int row = p >> 3, cp = p & 7;
            int gm = m0 + row;
            float2 v = make_float2(0.f, 0.f);
            if (gm < T_N)
                v = *reinterpret_cast<const float2*>(&g_h3[(size_t)gm * F4 + kt + 2 * cp]);
            split_store(&sAh[row * PA + 2 * cp], &sAl[row * PA + 2 * cp], v);
        }
        LOAD_B(g_Bn2_hi, g_Bn2_lo, F4, FDIM, 256);
        __syncthreads();
        mma_chunk_t<2>(aH, aL, bHa, bLa, acc);
        __syncthreads();
    }

    #pragma unroll
    for (int mi = 0; mi < 2; mi++)
        #pragma unroll
        for (int h = 0; h < 2; h++) {
            int gm = m0 + wm0 + mi * 16 + (lane >> 2) + h * 8;
            if (gm >= T_N) continue;
            #pragma unroll
            for (int ni = 0; ni < 4; ni++) {
                int col = wn0 + ni * 8 + 2 * (lane & 3);
                float2 bb = *reinterpret_cast<const float2*>(b2b + col);
                float2 o;
                o.x = acc[mi * 4 + ni][h * 2 + 0] + bb.x;
                o.y = acc[mi * 4 + ni][h * 2 + 1] + bb.y;
                *reinterpret_cast<float2*>(&out[(size_t)gm * FDIM + col]) = o;
            }
        }
}

// ---------------------------------------------------------------------------
// BatchNorm
// ---------------------------------------------------------------------------
__global__ void bn_stats(const float* __restrict__ y) {
    int c = threadIdx.x & (FDIM - 1);
    int half = threadIdx.x >> 7;
    double s = 0.0, sq = 0.0;
    for (int m = blockIdx.x * 2 + half; m < T_N; m += gridDim.x * 2) {
        float v = y[(size_t)m * FDIM + c];
        s += v;
        sq += (double)v * (double)v;
    }
    atomicAdd(&g_sum[c], s);
    atomicAdd(&g_sumsq[c], sq);
}

__global__ void bn_norm(float* __restrict__ y,
                        const float* __restrict__ gamma,
                        const float* __restrict__ beta) {
    size_t idx = (size_t)blockIdx.x * blockDim.x + threadIdx.x;
    if (idx >= (size_t)T_N * FDIM) return;
    int c = (int)(idx & (FDIM - 1));
    double mean = g_sum[c] / (double)T_N;
    double var = g_sumsq[c] / (double)T_N - mean * mean;
    float scale = rsqrtf((float)var + BN_EPS) * gamma[c];
    y[idx] = (float)((double)y[idx] - mean) * scale + beta[c];
}

extern "C" void kernel_launch(void* const* d_in, const int* in_sizes, int n_in,
                              void* d_out, int out_size) {
    const float* x_s       = (const float*)d_in[0];
    const float* x_t       = (const float*)d_in[1];
    const float* edge_attr = (const float*)d_in[2];
    const float* u         = (const float*)d_in[3];
    const int*   eidx      = (const int*)d_in[4];
    const float* W1a       = (const float*)d_in[5];
    const float* b1a       = (const float*)d_in[6];
    const float* W1b       = (const float*)d_in[7];
    const float* b1b       = (const float*)d_in[8];
    const float* W2a       = (const float*)d_in[9];
    const float* b2a       = (const float*)d_in[10];
    const float* W2b       = (const float*)d_in[11];
    const float* b2b       = (const float*)d_in[12];
    const float* gamma     = (const float*)d_in[13];
    const float* beta      = (const float*)d_in[14];
    float* out = (float*)d_out;

    zero_kernel<<<1024, 256>>>();
    compute_Wmid<<<F2, 512>>>(W1b, W2a);
    compute_vecs<<<1, 512>>>(b1b, u, W2a, b2a);
    convert_Bpre<<<(F2 * FDIM + 255) / 256, 256>>>(W1a);
    convert_Bedge<<<(F2 * FDIM + 255) / 256, 256>>>(W1a);
    convert_Bn1<<<(F4 * 384 + 255) / 256, 256>>>(W2a);
    convert_Bn2<<<(FDIM * F4 + 255) / 256, 256>>>(W2b);

    int mblk = (S_N + TBM - 1) / TBM;               // 782
    gemm_pre<<<mblk, 256>>>(x_s, b1a);

    int eblk = (E_N + TBME - 1) / TBME;             // 4688
    gemm_edge<<<eblk, 512>>>(edge_attr, eidx);

    dim3 gN1(2, mblk);
    gemm_node1<<<gN1, 256>>>(x_t);

    gemm_node2<<<mblk, 256>>>(b2b, out);

    bn_stats<<<512, 256>>>(out);
    bn_norm<<<(T_N * FDIM + 255) / 256, 256>>>(out, gamma, beta);
}